// round 13
// baseline (speedup 1.0000x reference)
#include <cuda_runtime.h>
#include <cuda_fp16.h>
#include <cstdint>

// ---------------------------------------------------------------------------
// GCN, 4 layers:  h_out = relu( (A @ h) @ W + b )   (SpMM first, then GEMM)
// FP16 datapath; GEMM mma.sync m16n8k16 (ldmatrix A, fragment-permuted W).
// NEW: software pipeline across layers — GEMM and SpMM split into column
// halves on two streams; S_{l+1} half-a overlaps G_l half-b. 3-buffer
// rotation (B0->B1->B2->B0...) removes all WAR hazards.
// ---------------------------------------------------------------------------

#define NMAX     10016
#define EMAX     200032
#define CDIM     512

__device__ __half   g_hbuf[3][NMAX * CDIM];  // rotating feature buffers
__device__ __half   g_wh[4][CDIM * CDIM];    // fp16, fragment-permuted weights
__device__ int2     g_edge[EMAX];            // packed (src, w-bits), dst-sorted
__device__ int      g_ptr[NMAX + 1];
__device__ int      g_deg[NMAX];             // RAW degree (no self loop)
__device__ int      g_cur[NMAX];
__device__ float    g_dinv[NMAX];
__device__ unsigned g_state[64];             // lookback: (flag<<30)|sum

__device__ __forceinline__ int clampi(int v, int n) {
    return v < 0 ? 0 : (v >= n ? n - 1 : v);
}

__device__ __forceinline__ uint32_t smem_u32(const void* p) {
    uint32_t a;
    asm("{ .reg .u64 t; cvta.to.shared.u64 t, %1; cvt.u32.u64 %0, t; }"
        : "=r"(a) : "l"(p));
    return a;
}

#define CP_ASYNC16(dst, src) \
    asm volatile("cp.async.cg.shared.global [%0], [%1], 16;" \
                 :: "r"(dst), "l"(src) : "memory")
#define CP_COMMIT()  asm volatile("cp.async.commit_group;" ::: "memory")
#define CP_WAIT1()   asm volatile("cp.async.wait_group 1;" ::: "memory")
#define CP_WAIT0()   asm volatile("cp.async.wait_group 0;" ::: "memory")

#define LDMATRIX_X4(r0, r1, r2, r3, addr) \
    asm volatile("ldmatrix.sync.aligned.m8n8.x4.shared.b16 {%0,%1,%2,%3}, [%4];" \
                 : "=r"(r0), "=r"(r1), "=r"(r2), "=r"(r3) : "r"(addr))

#define LDS128U(r0, r1, r2, r3, addr) \
    asm volatile("ld.shared.v4.u32 {%0,%1,%2,%3}, [%4];" \
                 : "=r"(r0), "=r"(r1), "=r"(r2), "=r"(r3) : "r"(addr))

// ---------------------------- preprocessing --------------------------------

__global__ void count_kernel(const int* __restrict__ ei, int E, int n) {
    int e = blockIdx.x * blockDim.x + threadIdx.x;
    if (e < E) atomicAdd(&g_deg[clampi(ei[E + e], n)], 1);
}

// fused scan: dinv + exclusive scan of (deg_raw + 1), decoupled lookback.
__global__ void scan_fused(int n) {
    __shared__ int wexc[16];
    __shared__ int blk_excl;
    int b = blockIdx.x, t = threadIdx.x;
    int i = b * 512 + t;
    int d = 0;
    if (i < n) {
        d = g_deg[i] + 1;                    // +1 implicit self loop
        g_dinv[i] = rsqrtf((float)d);
    }
    int lane = t & 31, w = t >> 5;
    int x = d;
    #pragma unroll
    for (int off = 1; off < 32; off <<= 1) {
        int y = __shfl_up_sync(0xffffffffu, x, off);
        if (lane >= off) x += y;
    }
    if (lane == 31) wexc[w] = x;
    __syncthreads();
    if (w == 0 && lane < 16) {
        int v = wexc[lane];
        int z = v;
        #pragma unroll
        for (int off = 1; off < 16; off <<= 1) {
            int y = __shfl_up_sync(0x0000ffffu, z, off);
            if (lane >= off) z += y;
        }
        wexc[lane] = z - v;
        if (lane == 15) {
            unsigned blk_sum = (unsigned)z;
            if (b == 0) {
                atomicExch(&g_state[0], (2u << 30) | blk_sum);
                blk_excl = 0;
            } else {
                atomicExch(&g_state[b], (1u << 30) | blk_sum);
                unsigned excl = 0;
                for (int j = b - 1; j >= 0; j--) {
                    unsigned s;
                    do { s = atomicAdd(&g_state[j], 0u); } while ((s >> 30) == 0u);
                    excl += s & 0x3FFFFFFFu;
                    if ((s >> 30) == 2u) break;
                }
                atomicExch(&g_state[b], (2u << 30) | (excl + blk_sum));
                blk_excl = (int)excl;
            }
        }
    }
    __syncthreads();
    int excl = blk_excl + wexc[w] + x - d;
    if (i < n) g_ptr[i] = excl;
    if (i == n - 1) g_ptr[n] = excl + d;
}

// fill edges (atomic slots) + self loops (static slot ptr[c] + deg_raw[c])
__global__ void fill_kernel(const int* __restrict__ ei, int E, int n) {
    int e = blockIdx.x * blockDim.x + threadIdx.x;
    if (e < E) {
        int r = clampi(ei[e], n), c = clampi(ei[E + e], n);
        int pos = g_ptr[c] + atomicAdd(&g_cur[c], 1);
        if (pos < EMAX)
            g_edge[pos] = make_int2(r, __float_as_int(g_dinv[r] * g_dinv[c]));
    } else if (e < E + n) {
        int c = e - E;
        int pos = g_ptr[c] + g_deg[c];
        float dv = g_dinv[c];
        if (pos < EMAX)
            g_edge[pos] = make_int2(c, __float_as_int(dv * dv));
    }
}

// convert x to fp16 into B0
__global__ void xhalf_kernel(const float* __restrict__ x, int total4) {
    int i = blockIdx.x * blockDim.x + threadIdx.x;
    if (i < total4) {
        float4 v = ((const float4*)x)[i];
        half2* D = (half2*)g_hbuf[0];
        D[i * 2 + 0] = __floats2half2_rn(v.x, v.y);
        D[i * 2 + 1] = __floats2half2_rn(v.z, v.w);
    }
}

// ---- weight preprocessing: fp16 round + m16n8k16 fragment permutation -----
__device__ __forceinline__ void permWh(__half* dst, const float* __restrict__ W,
                                       int o, int ktbits) {
    int h    = o & 7;
    int lane = (o >> 3) & 31;
    int c    = (o >> 8) & 3;
    int wn2  = (o >> 10) & 1;
    int kk2  = (o >> 11) & 1;
    int rest = o >> 12;
    int kt   = rest & ((1 << ktbits) - 1);
    int nb   = rest >> ktbits;
    int tg = lane & 3, gp = lane >> 2;
    int nt = c * 2 + (h >> 2), hw = h & 3;
    int k  = kt * 32 + kk2 * 16 + (hw >> 1) * 8 + tg * 2 + (hw & 1);
    int n  = nb * 128 + wn2 * 64 + nt * 8 + gp;
    dst[o] = __float2half(W[k * CDIM + n]);
}

__global__ void wround_kernel(const float* __restrict__ W1,
                              const float* __restrict__ W2,
                              const float* __restrict__ W3,
                              const float* __restrict__ W4, int n1) {
    int o = blockIdx.x * blockDim.x + threadIdx.x;
    if (o < CDIM * CDIM) {
        permWh(g_wh[1], W2, o, 4);
        permWh(g_wh[2], W3, o, 4);
        permWh(g_wh[3], W4, o, 4);
        if (o < n1) permWh(g_wh[0], W1, o, 3);   // K=256 -> KT=8
    }
}

// ------------------------------- CSR SpMM ----------------------------------
// fp16 gather, fp32 accum, fp16 write; packed edges; unroll 4.
// Handles uint4 columns [offq, offq+blockDim) of a rowq-uint4-wide buffer.
__global__ void spmm_h(int srcsel, int dstsel, int rowq, int offq)
{
    int v = blockIdx.x;
    int t = threadIdx.x + offq;
    const uint4* S = (const uint4*)g_hbuf[srcsel];
    uint4* D = (uint4*)g_hbuf[dstsel];

    int beg = g_ptr[v], end = g_ptr[v + 1];
    float f[8];
    #pragma unroll
    for (int j = 0; j < 8; j++) f[j] = 0.f;

    int e = beg;
    for (; e + 3 < end; e += 4) {
        int2 e0 = g_edge[e],     e1 = g_edge[e + 1];
        int2 e2 = g_edge[e + 2], e3 = g_edge[e + 3];
        uint4 u0 = S[e0.x * rowq + t];
        uint4 u1 = S[e1.x * rowq + t];
        uint4 u2 = S[e2.x * rowq + t];
        uint4 u3 = S[e3.x * rowq + t];
        float w0 = __int_as_float(e0.y), w1 = __int_as_float(e1.y);
        float w2 = __int_as_float(e2.y), w3 = __int_as_float(e3.y);
        const half2* p0 = (const half2*)&u0;
        const half2* p1 = (const half2*)&u1;
        const half2* p2 = (const half2*)&u2;
        const half2* p3 = (const half2*)&u3;
        #pragma unroll
        for (int q = 0; q < 4; q++) {
            float2 a = __half22float2(p0[q]);
            float2 b = __half22float2(p1[q]);
            float2 cc = __half22float2(p2[q]);
            float2 dd = __half22float2(p3[q]);
            f[q * 2 + 0] += w0 * a.x + w1 * b.x + w2 * cc.x + w3 * dd.x;
            f[q * 2 + 1] += w0 * a.y + w1 * b.y + w2 * cc.y + w3 * dd.y;
        }
    }
    for (; e < end; e++) {
        int2 e0 = g_edge[e];
        float w0 = __int_as_float(e0.y);
        uint4 u0 = S[e0.x * rowq + t];
        const half2* p0 = (const half2*)&u0;
        #pragma unroll
        for (int q = 0; q < 4; q++) {
            float2 a = __half22float2(p0[q]);
            f[q * 2 + 0] += w0 * a.x;
            f[q * 2 + 1] += w0 * a.y;
        }
    }

    uint4 o;
    half2* op = (half2*)&o;
    #pragma unroll
    for (int q = 0; q < 4; q++)
        op[q] = __floats2half2_rn(f[q * 2], f[q * 2 + 1]);
    D[v * rowq + t] = o;
}

// --------------------------- fp16 GEMM (mma.sync) --------------------------

__device__ __forceinline__ void mma_f16(float* c, const uint32_t* a,
                                        uint32_t b0, uint32_t b1) {
    asm volatile(
        "mma.sync.aligned.m16n8k16.row.col.f32.f16.f16.f32 "
        "{%0,%1,%2,%3}, {%4,%5,%6,%7}, {%8,%9}, {%0,%1,%2,%3};"
        : "+f"(c[0]), "+f"(c[1]), "+f"(c[2]), "+f"(c[3])
        : "r"(a[0]), "r"(a[1]), "r"(a[2]), "r"(a[3]), "r"(b0), "r"(b1));
}

#define AROWH 40   // A smem row stride in halves (80 B)

__global__ __launch_bounds__(128)
void gemm_h(const __half* __restrict__ Wh, const float* __restrict__ bias,
            float* __restrict__ dout, int M, int K, int insel, int outsel,
            int relu, int nbb)
{
    __shared__ __align__(16) __half Ah[3][64 * AROWH];  // 5120 B / stage
    __shared__ __align__(16) __half Bh[3][4096];        // 8192 B / stage
    __shared__ float sbias[128];

    const __half* A = g_hbuf[insel];
    __half* C16 = (outsel < 0) ? nullptr : g_hbuf[outsel];

    int tid  = threadIdx.x;
    int bm   = blockIdx.x * 64;
    int nb   = nbb + blockIdx.y;        // global n-block (0..3)
    int bn   = nb * 128;
    int wid  = tid >> 5, lane = tid & 31;
    int wm   = (wid >> 1) * 32;
    int wn   = (wid & 1) * 64;
    int wn2  = wid & 1;
    int tg   = lane & 3, gp = lane >> 2;

    sbias[tid] = bias[bn + tid];

    float acc[2][8][4];
    #pragma unroll
    for (int mt = 0; mt < 2; mt++)
        #pragma unroll
        for (int nt = 0; nt < 8; nt++)
            #pragma unroll
            for (int q = 0; q < 4; q++) acc[mt][nt][q] = 0.f;

    int a_row = tid >> 2, a_seg = tid & 3;
    int gr0 = bm + a_row;      if (gr0 >= M) gr0 = M - 1;
    int gr1 = bm + a_row + 32; if (gr1 >= M) gr1 = M - 1;

    uint32_t AhB[3], BhB[3];
    uint32_t sa0[3], sa1[3];
    #pragma unroll
    for (int s = 0; s < 3; s++) {
        AhB[s] = smem_u32(&Ah[s][0]);
        BhB[s] = smem_u32(&Bh[s][0]);
        sa0[s] = AhB[s] + (a_row * AROWH + a_seg * 8) * 2;
        sa1[s] = sa0[s] + 32 * AROWH * 2;
    }

    int lrow  = (lane & 7) + ((lane >> 3) & 1) * 8;
    int lcol  = (lane >> 4) & 1;
    uint32_t lmoff[2];
    #pragma unroll
    for (int mt = 0; mt < 2; mt++)
        lmoff[mt] = ((wm + mt * 16 + lrow) * AROWH) * 2 + lcol * 16;

    int ktiles = K >> 5;

    auto prefetch = [&](int kt) {
        int s  = kt % 3;
        const __half* a0p = A + (size_t)gr0 * K + kt * 32 + a_seg * 8;
        const __half* a1p = A + (size_t)gr1 * K + kt * 32 + a_seg * 8;
        CP_ASYNC16(sa0[s], a0p);
        CP_ASYNC16(sa1[s], a1p);
        const __half* src = Wh + (((size_t)(nb * ktiles + kt)) << 12) + (size_t)tid * 8;
        uint32_t bd = BhB[s] + tid * 16;
        #pragma unroll
        for (int i = 0; i < 4; i++)
            CP_ASYNC16(bd + i * 2048, src + i * 1024);
        CP_COMMIT();
    };

    prefetch(0);
    if (ktiles > 1) prefetch(1); else CP_COMMIT();

    for (int kt = 0; kt < ktiles; kt++) {
        if (kt + 1 < ktiles) CP_WAIT1(); else CP_WAIT0();
        __syncthreads();

        int buf = kt % 3;
        #pragma unroll
        for (int kk2 = 0; kk2 < 2; kk2++) {
            uint32_t a[2][4];
            #pragma unroll
            for (int mt = 0; mt < 2; mt++)
                LDMATRIX_X4(a[mt][0], a[mt][1], a[mt][2], a[mt][3],
                            AhB[buf] + lmoff[mt] + kk2 * 32);
            uint32_t b[8][2];
            #pragma unroll
            for (int c = 0; c < 4; c++) {
                uint32_t q0, q1, q2, q3;
                LDS128U(q0, q1, q2, q3,
                        BhB[buf] + ((kk2 * 2 + wn2) * 4 + c) * 512 + lane * 16);
                b[c * 2 + 0][0] = q0; b[c * 2 + 0][1] = q1;
                b[c * 2 + 1][0] = q2; b[c * 2 + 1][1] = q3;
            }
            #pragma unroll
            for (int mt = 0; mt < 2; mt++)
                #pragma unroll
                for (int nt = 0; nt < 8; nt++)
                    mma_f16(acc[mt][nt], a[mt], b[nt][0], b[nt][1]);
        }

        if (kt + 2 < ktiles) prefetch(kt + 2);
    }

    // epilogue: + bias (smem), optional relu; fp16 to g_hbuf or fp32 to dout
    #pragma unroll
    for (int mt = 0; mt < 2; mt++) {
        #pragma unroll
        for (int nt = 0; nt < 8; nt++) {
            int r = bm + wm + mt * 16 + gp;
            int cl = wn + nt * 8 + tg * 2;
            int c = bn + cl;
            float bb0 = sbias[cl], bb1 = sbias[cl + 1];
            float v0 = acc[mt][nt][0] + bb0, v1 = acc[mt][nt][1] + bb1;
            float v2 = acc[mt][nt][2] + bb0, v3 = acc[mt][nt][3] + bb1;
            if (relu) {
                v0 = fmaxf(v0, 0.f); v1 = fmaxf(v1, 0.f);
                v2 = fmaxf(v2, 0.f); v3 = fmaxf(v3, 0.f);
            }
            if (outsel < 0) {
                if (r < M)     *(float2*)&dout[(size_t)r * CDIM + c]       = make_float2(v0, v1);
                if (r + 8 < M) *(float2*)&dout[(size_t)(r + 8) * CDIM + c] = make_float2(v2, v3);
            } else {
                if (r < M)     *(half2*)&C16[(size_t)r * CDIM + c]       = __floats2half2_rn(v0, v1);
                if (r + 8 < M) *(half2*)&C16[(size_t)(r + 8) * CDIM + c] = __floats2half2_rn(v2, v3);
            }
        }
    }
}

// ------------------------------- driver ------------------------------------

extern "C" void kernel_launch(void* const* d_in, const int* in_sizes, int n_in,
                              void* d_out, int out_size)
{
    const float* x  = (const float*)d_in[0];
    const int*   ei = (const int*)d_in[1];      // int64 downcast to int32
    const float* W1 = (const float*)d_in[2];
    const float* b1 = (const float*)d_in[3];
    const float* W2 = (const float*)d_in[4];
    const float* b2 = (const float*)d_in[5];
    const float* W3 = (const float*)d_in[6];
    const float* b3 = (const float*)d_in[7];
    const float* W4 = (const float*)d_in[8];
    const float* b4 = (const float*)d_in[9];
    float* out = (float*)d_out;

    int Cin = in_sizes[2] / CDIM;         // 256
    int N   = in_sizes[0] / Cin;          // 10000
    int E   = in_sizes[1] / 2;            // 160000
    int nc  = (N + 511) / 512;            // 20 chunks

    static __half* wh_host[4] = {nullptr, nullptr, nullptr, nullptr};
    static void* deg_p = nullptr; static void* cur_p = nullptr;
    static void* st_p = nullptr;
    static cudaStream_t sB = nullptr;
    static cudaEvent_t evFork = nullptr, evJoin = nullptr;
    static cudaEvent_t eG[3], eS[3];
    if (!wh_host[0]) {
        void* p;
        cudaGetSymbolAddress(&p, g_wh);
        for (int l = 0; l < 4; l++)
            wh_host[l] = (__half*)p + (size_t)l * CDIM * CDIM;
        cudaGetSymbolAddress(&deg_p, g_deg);
        cudaGetSymbolAddress(&cur_p, g_cur);
        cudaGetSymbolAddress(&st_p, g_state);
        cudaStreamCreateWithFlags(&sB, cudaStreamNonBlocking);
        cudaEventCreateWithFlags(&evFork, cudaEventDisableTiming);
        cudaEventCreateWithFlags(&evJoin, cudaEventDisableTiming);
        for (int i = 0; i < 3; i++) {
            cudaEventCreateWithFlags(&eG[i], cudaEventDisableTiming);
            cudaEventCreateWithFlags(&eS[i], cudaEventDisableTiming);
        }
    }

    // fork: weight/feature conversion on side stream
    cudaEventRecord(evFork, 0);
    cudaStreamWaitEvent(sB, evFork, 0);
    wround_kernel<<<(CDIM * CDIM + 255) / 256, 256, 0, sB>>>(W1, W2, W3, W4,
                                                            Cin * CDIM);
    xhalf_kernel<<<(N * Cin / 4 + 255) / 256, 256, 0, sB>>>(x, N * Cin / 4);
    cudaEventRecord(evJoin, sB);

    // graph preprocessing (main stream)
    cudaMemsetAsync(deg_p, 0, N * sizeof(int), 0);
    cudaMemsetAsync(cur_p, 0, N * sizeof(int), 0);
    cudaMemsetAsync(st_p, 0, 64 * sizeof(unsigned), 0);
    count_kernel<<<(E + 255) / 256, 256>>>(ei, E, N);
    scan_fused<<<nc, 512>>>(N);
    fill_kernel<<<(E + N + 255) / 256, 256>>>(ei, E, N);
    cudaStreamWaitEvent(0, evJoin, 0);   // join before layers

    dim3 gh((N + 63) / 64, 2);           // half-N GEMM grid (157, 2)

    // Buffer rotation: B0=H0, S:B0->B1, G1:B1->B2, S2:B2->B0, G2:B0->B1,
    // S3:B1->B2, G3:B2->B0, S4:B0->B1, G4:B1->out.
    // L1: full SpMM (256 cols), then half GEMMs
    spmm_h<<<N, 32>>>(0, 1, 32, 0);                                   // S1
    gemm_h<<<gh, 128>>>(wh_host[0], b1, nullptr, N, Cin, 1, 2, 1, 0); // G1a
    cudaEventRecord(eG[0], 0);
    gemm_h<<<gh, 128>>>(wh_host[0], b1, nullptr, N, Cin, 1, 2, 1, 2); // G1b
    // L2: S2a (sB, after G1a) overlaps G1b
    cudaStreamWaitEvent(sB, eG[0], 0);
    spmm_h<<<N, 32, 0, sB>>>(2, 0, 64, 0);                            // S2a
    cudaEventRecord(eS[0], sB);
    spmm_h<<<N, 32>>>(2, 0, 64, 32);                                  // S2b
    cudaStreamWaitEvent(0, eS[0], 0);
    gemm_h<<<gh, 128>>>(wh_host[1], b2, nullptr, N, CDIM, 0, 1, 1, 0);// G2a
    cudaEventRecord(eG[1], 0);
    gemm_h<<<gh, 128>>>(wh_host[1], b2, nullptr, N, CDIM, 0, 1, 1, 2);// G2b
    // L3
    cudaStreamWaitEvent(sB, eG[1], 0);
    spmm_h<<<N, 32, 0, sB>>>(1, 2, 64, 0);                            // S3a
    cudaEventRecord(eS[1], sB);
    spmm_h<<<N, 32>>>(1, 2, 64, 32);                                  // S3b
    cudaStreamWaitEvent(0, eS[1], 0);
    gemm_h<<<gh, 128>>>(wh_host[2], b3, nullptr, N, CDIM, 2, 0, 1, 0);// G3a
    cudaEventRecord(eG[2], 0);
    gemm_h<<<gh, 128>>>(wh_host[2], b3, nullptr, N, CDIM, 2, 0, 1, 2);// G3b
    // L4
    cudaStreamWaitEvent(sB, eG[2], 0);
    spmm_h<<<N, 32, 0, sB>>>(0, 1, 64, 0);                            // S4a
    cudaEventRecord(eS[2], sB);
    spmm_h<<<N, 32>>>(0, 1, 64, 32);                                  // S4b
    cudaStreamWaitEvent(0, eS[2], 0);
    gemm_h<<<gh, 128>>>(wh_host[3], b4, out, N, CDIM, 1, -1, 0, 0);   // G4a
    gemm_h<<<gh, 128>>>(wh_host[3], b4, out, N, CDIM, 1, -1, 0, 2);   // G4b
}

// round 15
// speedup vs baseline: 1.0983x; 1.0983x over previous
#include <cuda_runtime.h>
#include <cuda_fp16.h>
#include <cstdint>

// ---------------------------------------------------------------------------
// GCN, 4 layers:  h_out = relu( (A @ h) @ W + b )   (SpMM first, then GEMM)
// FP16 datapath; GEMM mma.sync m16n8k16 (ldmatrix A, fragment-permuted W).
// R15 = R14 resubmission (container infra failure, kernel never ran):
// single-stream chain (R11) + ILP-2 in fill/count preproc kernels.
// ---------------------------------------------------------------------------

#define NMAX     10016
#define EMAX     200032
#define CDIM     512

__device__ __half   g_hbuf[2][NMAX * CDIM];  // ping-pong feature buffers
__device__ __half   g_wh[4][CDIM * CDIM];    // fp16, fragment-permuted weights
__device__ int2     g_edge[EMAX];            // packed (src, w-bits), dst-sorted
__device__ int      g_ptr[NMAX + 1];
__device__ int      g_deg[NMAX];             // RAW degree (no self loop)
__device__ int      g_cur[NMAX];
__device__ float    g_dinv[NMAX];
__device__ unsigned g_state[64];             // lookback: (flag<<30)|sum

__device__ __forceinline__ int clampi(int v, int n) {
    return v < 0 ? 0 : (v >= n ? n - 1 : v);
}

__device__ __forceinline__ uint32_t smem_u32(const void* p) {
    uint32_t a;
    asm("{ .reg .u64 t; cvta.to.shared.u64 t, %1; cvt.u32.u64 %0, t; }"
        : "=r"(a) : "l"(p));
    return a;
}

#define CP_ASYNC16(dst, src) \
    asm volatile("cp.async.cg.shared.global [%0], [%1], 16;" \
                 :: "r"(dst), "l"(src) : "memory")
#define CP_COMMIT()  asm volatile("cp.async.commit_group;" ::: "memory")
#define CP_WAIT1()   asm volatile("cp.async.wait_group 1;" ::: "memory")
#define CP_WAIT0()   asm volatile("cp.async.wait_group 0;" ::: "memory")

#define LDMATRIX_X4(r0, r1, r2, r3, addr) \
    asm volatile("ldmatrix.sync.aligned.m8n8.x4.shared.b16 {%0,%1,%2,%3}, [%4];" \
                 : "=r"(r0), "=r"(r1), "=r"(r2), "=r"(r3) : "r"(addr))

#define LDS128U(r0, r1, r2, r3, addr) \
    asm volatile("ld.shared.v4.u32 {%0,%1,%2,%3}, [%4];" \
                 : "=r"(r0), "=r"(r1), "=r"(r2), "=r"(r3) : "r"(addr))

// ---------------------------- preprocessing --------------------------------

// ILP-2: each thread counts two edges (int2 col loads; E is even)
__global__ void count_kernel(const int* __restrict__ ei, int E, int n) {
    int i = blockIdx.x * blockDim.x + threadIdx.x;
    int e = i * 2;
    if (e + 1 < E) {
        int2 c = *(const int2*)&ei[E + e];
        atomicAdd(&g_deg[clampi(c.x, n)], 1);
        atomicAdd(&g_deg[clampi(c.y, n)], 1);
    } else if (e < E) {
        atomicAdd(&g_deg[clampi(ei[E + e], n)], 1);
    }
}

// fused scan: dinv + exclusive scan of (deg_raw + 1), decoupled lookback.
__global__ void scan_fused(int n) {
    __shared__ int wexc[16];
    __shared__ int blk_excl;
    int b = blockIdx.x, t = threadIdx.x;
    int i = b * 512 + t;
    int d = 0;
    if (i < n) {
        d = g_deg[i] + 1;                    // +1 implicit self loop
        g_dinv[i] = rsqrtf((float)d);
    }
    int lane = t & 31, w = t >> 5;
    int x = d;
    #pragma unroll
    for (int off = 1; off < 32; off <<= 1) {
        int y = __shfl_up_sync(0xffffffffu, x, off);
        if (lane >= off) x += y;
    }
    if (lane == 31) wexc[w] = x;
    __syncthreads();
    if (w == 0 && lane < 16) {
        int v = wexc[lane];
        int z = v;
        #pragma unroll
        for (int off = 1; off < 16; off <<= 1) {
            int y = __shfl_up_sync(0x0000ffffu, z, off);
            if (lane >= off) z += y;
        }
        wexc[lane] = z - v;
        if (lane == 15) {
            unsigned blk_sum = (unsigned)z;
            if (b == 0) {
                atomicExch(&g_state[0], (2u << 30) | blk_sum);
                blk_excl = 0;
            } else {
                atomicExch(&g_state[b], (1u << 30) | blk_sum);
                unsigned excl = 0;
                for (int j = b - 1; j >= 0; j--) {
                    unsigned s;
                    do { s = atomicAdd(&g_state[j], 0u); } while ((s >> 30) == 0u);
                    excl += s & 0x3FFFFFFFu;
                    if ((s >> 30) == 2u) break;
                }
                atomicExch(&g_state[b], (2u << 30) | (excl + blk_sum));
                blk_excl = (int)excl;
            }
        }
    }
    __syncthreads();
    int excl = blk_excl + wexc[w] + x - d;
    if (i < n) g_ptr[i] = excl;
    if (i == n - 1) g_ptr[n] = excl + d;
}

// fill: ILP-2 on edges (int2 row/col loads) + self loops at static slots
__global__ void fill_kernel(const int* __restrict__ ei, int E, int n) {
    int i = blockIdx.x * blockDim.x + threadIdx.x;
    int T = E >> 1;                          // E is even
    if (i < T) {
        int e = i * 2;
        int2 rr = *(const int2*)&ei[e];
        int2 cc = *(const int2*)&ei[E + e];
        int r0 = clampi(rr.x, n), c0 = clampi(cc.x, n);
        int r1 = clampi(rr.y, n), c1 = clampi(cc.y, n);
        float d0 = g_dinv[r0] * g_dinv[c0];
        float d1 = g_dinv[r1] * g_dinv[c1];
        int p0 = g_ptr[c0] + atomicAdd(&g_cur[c0], 1);
        int p1 = g_ptr[c1] + atomicAdd(&g_cur[c1], 1);
        if (p0 < EMAX) g_edge[p0] = make_int2(r0, __float_as_int(d0));
        if (p1 < EMAX) g_edge[p1] = make_int2(r1, __float_as_int(d1));
    } else if (i < T + n) {
        int c = i - T;
        int pos = g_ptr[c] + g_deg[c];       // last slot of c's segment
        float dv = g_dinv[c];
        if (pos < EMAX)
            g_edge[pos] = make_int2(c, __float_as_int(dv * dv));
    }
}

// convert x to fp16 into B0 (vectorized)
__global__ void xhalf_kernel(const float* __restrict__ x, int total4) {
    int i = blockIdx.x * blockDim.x + threadIdx.x;
    if (i < total4) {
        float4 v = ((const float4*)x)[i];
        half2* D = (half2*)g_hbuf[0];
        D[i * 2 + 0] = __floats2half2_rn(v.x, v.y);
        D[i * 2 + 1] = __floats2half2_rn(v.z, v.w);
    }
}

// ---- weight preprocessing: fp16 round + m16n8k16 fragment permutation -----
__device__ __forceinline__ void permWh(__half* dst, const float* __restrict__ W,
                                       int o, int ktbits) {
    int h    = o & 7;
    int lane = (o >> 3) & 31;
    int c    = (o >> 8) & 3;
    int wn2  = (o >> 10) & 1;
    int kk2  = (o >> 11) & 1;
    int rest = o >> 12;
    int kt   = rest & ((1 << ktbits) - 1);
    int nb   = rest >> ktbits;
    int tg = lane & 3, gp = lane >> 2;
    int nt = c * 2 + (h >> 2), hw = h & 3;
    int k  = kt * 32 + kk2 * 16 + (hw >> 1) * 8 + tg * 2 + (hw & 1);
    int n  = nb * 128 + wn2 * 64 + nt * 8 + gp;
    dst[o] = __float2half(W[k * CDIM + n]);
}

__global__ void wround_kernel(const float* __restrict__ W1,
                              const float* __restrict__ W2,
                              const float* __restrict__ W3,
                              const float* __restrict__ W4, int n1) {
    int o = blockIdx.x * blockDim.x + threadIdx.x;
    if (o < CDIM * CDIM) {
        permWh(g_wh[1], W2, o, 4);
        permWh(g_wh[2], W3, o, 4);
        permWh(g_wh[3], W4, o, 4);
        if (o < n1) permWh(g_wh[0], W1, o, 3);   // K=256 -> KT=8
    }
}

// ------------------------------- CSR SpMM ----------------------------------
// fp16 gather, fp32 accum, fp16 write; packed edges; unroll 4.
__global__ void spmm_h(int srcsel, int dstsel, int c8)
{
    int v = blockIdx.x;
    int t = threadIdx.x;
    const uint4* S = (const uint4*)g_hbuf[srcsel];
    uint4* D = (uint4*)g_hbuf[dstsel];

    int beg = g_ptr[v], end = g_ptr[v + 1];
    float f[8];
    #pragma unroll
    for (int j = 0; j < 8; j++) f[j] = 0.f;

    int e = beg;
    for (; e + 3 < end; e += 4) {
        int2 e0 = g_edge[e],     e1 = g_edge[e + 1];
        int2 e2 = g_edge[e + 2], e3 = g_edge[e + 3];
        uint4 u0 = S[e0.x * c8 + t];
        uint4 u1 = S[e1.x * c8 + t];
        uint4 u2 = S[e2.x * c8 + t];
        uint4 u3 = S[e3.x * c8 + t];
        float w0 = __int_as_float(e0.y), w1 = __int_as_float(e1.y);
        float w2 = __int_as_float(e2.y), w3 = __int_as_float(e3.y);
        const half2* p0 = (const half2*)&u0;
        const half2* p1 = (const half2*)&u1;
        const half2* p2 = (const half2*)&u2;
        const half2* p3 = (const half2*)&u3;
        #pragma unroll
        for (int q = 0; q < 4; q++) {
            float2 a = __half22float2(p0[q]);
            float2 b = __half22float2(p1[q]);
            float2 cc = __half22float2(p2[q]);
            float2 dd = __half22float2(p3[q]);
            f[q * 2 + 0] += w0 * a.x + w1 * b.x + w2 * cc.x + w3 * dd.x;
            f[q * 2 + 1] += w0 * a.y + w1 * b.y + w2 * cc.y + w3 * dd.y;
        }
    }
    for (; e < end; e++) {
        int2 e0 = g_edge[e];
        float w0 = __int_as_float(e0.y);
        uint4 u0 = S[e0.x * c8 + t];
        const half2* p0 = (const half2*)&u0;
        #pragma unroll
        for (int q = 0; q < 4; q++) {
            float2 a = __half22float2(p0[q]);
            f[q * 2 + 0] += w0 * a.x;
            f[q * 2 + 1] += w0 * a.y;
        }
    }

    uint4 o;
    half2* op = (half2*)&o;
    #pragma unroll
    for (int q = 0; q < 4; q++)
        op[q] = __floats2half2_rn(f[q * 2], f[q * 2 + 1]);
    D[v * c8 + t] = o;
}

// --------------------------- fp16 GEMM (mma.sync) --------------------------

__device__ __forceinline__ void mma_f16(float* c, const uint32_t* a,
                                        uint32_t b0, uint32_t b1) {
    asm volatile(
        "mma.sync.aligned.m16n8k16.row.col.f32.f16.f16.f32 "
        "{%0,%1,%2,%3}, {%4,%5,%6,%7}, {%8,%9}, {%0,%1,%2,%3};"
        : "+f"(c[0]), "+f"(c[1]), "+f"(c[2]), "+f"(c[3])
        : "r"(a[0]), "r"(a[1]), "r"(a[2]), "r"(a[3]), "r"(b0), "r"(b1));
}

#define AROWH 40   // A smem row stride in halves (80 B)

__global__ __launch_bounds__(128)
void gemm_h(const __half* __restrict__ Wh, const float* __restrict__ bias,
            float* __restrict__ dout, int M, int K, int insel, int outsel,
            int relu)
{
    __shared__ __align__(16) __half Ah[3][64 * AROWH];  // 5120 B / stage
    __shared__ __align__(16) __half Bh[3][4096];        // 8192 B / stage
    __shared__ float sbias[128];

    const __half* A = g_hbuf[insel];
    __half* C16 = (outsel < 0) ? nullptr : g_hbuf[outsel];

    int tid  = threadIdx.x;
    int bm   = blockIdx.x * 64;
    int nb   = blockIdx.y;
    int bn   = nb * 128;
    int wid  = tid >> 5, lane = tid & 31;
    int wm   = (wid >> 1) * 32;
    int wn   = (wid & 1) * 64;
    int wn2  = wid & 1;
    int tg   = lane & 3, gp = lane >> 2;

    sbias[tid] = bias[bn + tid];

    float acc[2][8][4];
    #pragma unroll
    for (int mt = 0; mt < 2; mt++)
        #pragma unroll
        for (int nt = 0; nt < 8; nt++)
            #pragma unroll
            for (int q = 0; q < 4; q++) acc[mt][nt][q] = 0.f;

    int a_row = tid >> 2, a_seg = tid & 3;
    int gr0 = bm + a_row;      if (gr0 >= M) gr0 = M - 1;
    int gr1 = bm + a_row + 32; if (gr1 >= M) gr1 = M - 1;

    uint32_t AhB[3], BhB[3];
    uint32_t sa0[3], sa1[3];
    #pragma unroll
    for (int s = 0; s < 3; s++) {
        AhB[s] = smem_u32(&Ah[s][0]);
        BhB[s] = smem_u32(&Bh[s][0]);
        sa0[s] = AhB[s] + (a_row * AROWH + a_seg * 8) * 2;
        sa1[s] = sa0[s] + 32 * AROWH * 2;
    }

    int lrow  = (lane & 7) + ((lane >> 3) & 1) * 8;
    int lcol  = (lane >> 4) & 1;
    uint32_t lmoff[2];
    #pragma unroll
    for (int mt = 0; mt < 2; mt++)
        lmoff[mt] = ((wm + mt * 16 + lrow) * AROWH) * 2 + lcol * 16;

    int ktiles = K >> 5;

    auto prefetch = [&](int kt) {
        int s  = kt % 3;
        const __half* a0p = A + (size_t)gr0 * K + kt * 32 + a_seg * 8;
        const __half* a1p = A + (size_t)gr1 * K + kt * 32 + a_seg * 8;
        CP_ASYNC16(sa0[s], a0p);
        CP_ASYNC16(sa1[s], a1p);
        const __half* src = Wh + (((size_t)(nb * ktiles + kt)) << 12) + (size_t)tid * 8;
        uint32_t bd = BhB[s] + tid * 16;
        #pragma unroll
        for (int i = 0; i < 4; i++)
            CP_ASYNC16(bd + i * 2048, src + i * 1024);
        CP_COMMIT();
    };

    prefetch(0);
    if (ktiles > 1) prefetch(1); else CP_COMMIT();

    for (int kt = 0; kt < ktiles; kt++) {
        if (kt + 1 < ktiles) CP_WAIT1(); else CP_WAIT0();
        __syncthreads();

        int buf = kt % 3;
        #pragma unroll
        for (int kk2 = 0; kk2 < 2; kk2++) {
            uint32_t a[2][4];
            #pragma unroll
            for (int mt = 0; mt < 2; mt++)
                LDMATRIX_X4(a[mt][0], a[mt][1], a[mt][2], a[mt][3],
                            AhB[buf] + lmoff[mt] + kk2 * 32);
            uint32_t b[8][2];
            #pragma unroll
            for (int c = 0; c < 4; c++) {
                uint32_t q0, q1, q2, q3;
                LDS128U(q0, q1, q2, q3,
                        BhB[buf] + ((kk2 * 2 + wn2) * 4 + c) * 512 + lane * 16);
                b[c * 2 + 0][0] = q0; b[c * 2 + 0][1] = q1;
                b[c * 2 + 1][0] = q2; b[c * 2 + 1][1] = q3;
            }
            #pragma unroll
            for (int mt = 0; mt < 2; mt++)
                #pragma unroll
                for (int nt = 0; nt < 8; nt++)
                    mma_f16(acc[mt][nt], a[mt], b[nt][0], b[nt][1]);
        }

        if (kt + 2 < ktiles) prefetch(kt + 2);
    }

    // epilogue: + bias (smem), optional relu; fp16 to g_hbuf or fp32 to dout
    #pragma unroll
    for (int mt = 0; mt < 2; mt++) {
        #pragma unroll
        for (int nt = 0; nt < 8; nt++) {
            int r = bm + wm + mt * 16 + gp;
            int cl = wn + nt * 8 + tg * 2;
            int c = bn + cl;
            float bb0 = sbias[cl], bb1 = sbias[cl + 1];
            float v0 = acc[mt][nt][0] + bb0, v1 = acc[mt][nt][1] + bb1;
            float v2 = acc[mt][nt][2] + bb0, v3 = acc[mt][nt][3] + bb1;
            if (relu) {
                v0 = fmaxf(v0, 0.f); v1 = fmaxf(v1, 0.f);
                v2 = fmaxf(v2, 0.f); v3 = fmaxf(v3, 0.f);
            }
            if (outsel < 0) {
                if (r < M)     *(float2*)&dout[(size_t)r * CDIM + c]       = make_float2(v0, v1);
                if (r + 8 < M) *(float2*)&dout[(size_t)(r + 8) * CDIM + c] = make_float2(v2, v3);
            } else {
                if (r < M)     *(half2*)&C16[(size_t)r * CDIM + c]       = __floats2half2_rn(v0, v1);
                if (r + 8 < M) *(half2*)&C16[(size_t)(r + 8) * CDIM + c] = __floats2half2_rn(v2, v3);
            }
        }
    }
}

// ------------------------------- driver ------------------------------------

extern "C" void kernel_launch(void* const* d_in, const int* in_sizes, int n_in,
                              void* d_out, int out_size)
{
    const float* x  = (const float*)d_in[0];
    const int*   ei = (const int*)d_in[1];      // int64 downcast to int32
    const float* W1 = (const float*)d_in[2];
    const float* b1 = (const float*)d_in[3];
    const float* W2 = (const float*)d_in[4];
    const float* b2 = (const float*)d_in[5];
    const float* W3 = (const float*)d_in[6];
    const float* b3 = (const float*)d_in[7];
    const float* W4 = (const float*)d_in[8];
    const float* b4 = (const float*)d_in[9];
    float* out = (float*)d_out;

    int Cin = in_sizes[2] / CDIM;         // 256
    int N   = in_sizes[0] / Cin;          // 10000
    int E   = in_sizes[1] / 2;            // 160000
    int nc  = (N + 511) / 512;            // 20 chunks

    static __half* wh_host[4] = {nullptr, nullptr, nullptr, nullptr};
    static void* deg_p = nullptr; static void* cur_p = nullptr;
    static void* st_p = nullptr;
    static cudaStream_t sB = nullptr;
    static cudaEvent_t evFork = nullptr, evJoin = nullptr;
    if (!wh_host[0]) {
        void* p;
        cudaGetSymbolAddress(&p, g_wh);
        for (int l = 0; l < 4; l++)
            wh_host[l] = (__half*)p + (size_t)l * CDIM * CDIM;
        cudaGetSymbolAddress(&deg_p, g_deg);
        cudaGetSymbolAddress(&cur_p, g_cur);
        cudaGetSymbolAddress(&st_p, g_state);
        cudaStreamCreateWithFlags(&sB, cudaStreamNonBlocking);
        cudaEventCreateWithFlags(&evFork, cudaEventDisableTiming);
        cudaEventCreateWithFlags(&evJoin, cudaEventDisableTiming);
    }

    // fork: weight/feature conversion on side stream
    cudaEventRecord(evFork, 0);
    cudaStreamWaitEvent(sB, evFork, 0);
    wround_kernel<<<(CDIM * CDIM + 255) / 256, 256, 0, sB>>>(W1, W2, W3, W4,
                                                            Cin * CDIM);
    xhalf_kernel<<<(N * Cin / 4 + 255) / 256, 256, 0, sB>>>(x, N * Cin / 4);
    cudaEventRecord(evJoin, sB);

    // graph preprocessing (main stream)
    cudaMemsetAsync(deg_p, 0, N * sizeof(int), 0);
    cudaMemsetAsync(cur_p, 0, N * sizeof(int), 0);
    cudaMemsetAsync(st_p, 0, 64 * sizeof(unsigned), 0);
    count_kernel<<<(E / 2 + 255) / 256, 256>>>(ei, E, N);
    scan_fused<<<nc, 512>>>(N);
    fill_kernel<<<(E / 2 + N + 255) / 256, 256>>>(ei, E, N);
    cudaStreamWaitEvent(0, evJoin, 0);   // join before layers

    dim3 ggrid((N + 63) / 64, CDIM / 128);   // (157, 4)

    // layer 1: aggregate x16 (256 cols) B0 -> B1 ; gemm K=256 -> B0
    spmm_h<<<N, Cin / 8>>>(0, 1, Cin / 8);
    gemm_h<<<ggrid, 128>>>(wh_host[0], b1, nullptr, N, Cin, 1, 0, 1);
    // layer 2
    spmm_h<<<N, CDIM / 8>>>(0, 1, CDIM / 8);
    gemm_h<<<ggrid, 128>>>(wh_host[1], b2, nullptr, N, CDIM, 1, 0, 1);
    // layer 3
    spmm_h<<<N, CDIM / 8>>>(0, 1, CDIM / 8);
    gemm_h<<<ggrid, 128>>>(wh_host[2], b3, nullptr, N, CDIM, 1, 0, 1);
    // layer 4 (no relu, fp32 out)
    spmm_h<<<N, CDIM / 8>>>(0, 1, CDIM / 8);
    gemm_h<<<ggrid, 128>>>(wh_host[3], b4, out, N, CDIM, 1, -1, 0);
}

// round 16
// speedup vs baseline: 1.1032x; 1.0044x over previous
#include <cuda_runtime.h>
#include <cuda_fp16.h>
#include <cstdint>

// ---------------------------------------------------------------------------
// GCN, 4 layers. Layer 1 computed as relu(A@(x@W1)+b1): the graph-independent
// GEMM x@W1 runs on a side stream CONCURRENTLY with graph preprocessing;
// bias+relu for layer 1 folds into the SpMM epilogue. Layers 2-4 stay
// (A@h)@W order (SpMM pure, bias+relu in GEMM epilogue).
// FP16 datapath; GEMM mma.sync m16n8k16 (ldmatrix A, fragment-permuted W).
// ---------------------------------------------------------------------------

#define NMAX     10016
#define EMAX     200032
#define CDIM     512

__device__ __half   g_hbuf[2][NMAX * CDIM];  // ping-pong feature buffers
__device__ __half   g_wh[4][CDIM * CDIM];    // fp16, fragment-permuted weights
__device__ int2     g_edge[EMAX];            // packed (src, w-bits), dst-sorted
__device__ int      g_ptr[NMAX + 1];
__device__ int      g_deg[NMAX];             // RAW degree (no self loop)
__device__ int      g_cur[NMAX];
__device__ float    g_dinv[NMAX];
__device__ unsigned g_state[64];             // lookback: (flag<<30)|sum

__device__ __forceinline__ int clampi(int v, int n) {
    return v < 0 ? 0 : (v >= n ? n - 1 : v);
}

__device__ __forceinline__ uint32_t smem_u32(const void* p) {
    uint32_t a;
    asm("{ .reg .u64 t; cvta.to.shared.u64 t, %1; cvt.u32.u64 %0, t; }"
        : "=r"(a) : "l"(p));
    return a;
}

#define CP_ASYNC16(dst, src) \
    asm volatile("cp.async.cg.shared.global [%0], [%1], 16;" \
                 :: "r"(dst), "l"(src) : "memory")
#define CP_COMMIT()  asm volatile("cp.async.commit_group;" ::: "memory")
#define CP_WAIT1()   asm volatile("cp.async.wait_group 1;" ::: "memory")
#define CP_WAIT0()   asm volatile("cp.async.wait_group 0;" ::: "memory")

#define LDMATRIX_X4(r0, r1, r2, r3, addr) \
    asm volatile("ldmatrix.sync.aligned.m8n8.x4.shared.b16 {%0,%1,%2,%3}, [%4];" \
                 : "=r"(r0), "=r"(r1), "=r"(r2), "=r"(r3) : "r"(addr))

#define LDS128U(r0, r1, r2, r3, addr) \
    asm volatile("ld.shared.v4.u32 {%0,%1,%2,%3}, [%4];" \
                 : "=r"(r0), "=r"(r1), "=r"(r2), "=r"(r3) : "r"(addr))

// ---------------------------- preprocessing --------------------------------

// ILP-2: each thread counts two edges (int2 col loads; E is even)
__global__ void count_kernel(const int* __restrict__ ei, int E, int n) {
    int i = blockIdx.x * blockDim.x + threadIdx.x;
    int e = i * 2;
    if (e + 1 < E) {
        int2 c = *(const int2*)&ei[E + e];
        atomicAdd(&g_deg[clampi(c.x, n)], 1);
        atomicAdd(&g_deg[clampi(c.y, n)], 1);
    } else if (e < E) {
        atomicAdd(&g_deg[clampi(ei[E + e], n)], 1);
    }
}

// fused scan: dinv + exclusive scan of (deg_raw + 1), decoupled lookback.
__global__ void scan_fused(int n) {
    __shared__ int wexc[16];
    __shared__ int blk_excl;
    int b = blockIdx.x, t = threadIdx.x;
    int i = b * 512 + t;
    int d = 0;
    if (i < n) {
        d = g_deg[i] + 1;                    // +1 implicit self loop
        g_dinv[i] = rsqrtf((float)d);
    }
    int lane = t & 31, w = t >> 5;
    int x = d;
    #pragma unroll
    for (int off = 1; off < 32; off <<= 1) {
        int y = __shfl_up_sync(0xffffffffu, x, off);
        if (lane >= off) x += y;
    }
    if (lane == 31) wexc[w] = x;
    __syncthreads();
    if (w == 0 && lane < 16) {
        int v = wexc[lane];
        int z = v;
        #pragma unroll
        for (int off = 1; off < 16; off <<= 1) {
            int y = __shfl_up_sync(0x0000ffffu, z, off);
            if (lane >= off) z += y;
        }
        wexc[lane] = z - v;
        if (lane == 15) {
            unsigned blk_sum = (unsigned)z;
            if (b == 0) {
                atomicExch(&g_state[0], (2u << 30) | blk_sum);
                blk_excl = 0;
            } else {
                atomicExch(&g_state[b], (1u << 30) | blk_sum);
                unsigned excl = 0;
                for (int j = b - 1; j >= 0; j--) {
                    unsigned s;
                    do { s = atomicAdd(&g_state[j], 0u); } while ((s >> 30) == 0u);
                    excl += s & 0x3FFFFFFFu;
                    if ((s >> 30) == 2u) break;
                }
                atomicExch(&g_state[b], (2u << 30) | (excl + blk_sum));
                blk_excl = (int)excl;
            }
        }
    }
    __syncthreads();
    int excl = blk_excl + wexc[w] + x - d;
    if (i < n) g_ptr[i] = excl;
    if (i == n - 1) g_ptr[n] = excl + d;
}

// fill: ILP-2 on edges + self loops at static slots
__global__ void fill_kernel(const int* __restrict__ ei, int E, int n) {
    int i = blockIdx.x * blockDim.x + threadIdx.x;
    int T = E >> 1;                          // E is even
    if (i < T) {
        int e = i * 2;
        int2 rr = *(const int2*)&ei[e];
        int2 cc = *(const int2*)&ei[E + e];
        int r0 = clampi(rr.x, n), c0 = clampi(cc.x, n);
        int r1 = clampi(rr.y, n), c1 = clampi(cc.y, n);
        float d0 = g_dinv[r0] * g_dinv[c0];
        float d1 = g_dinv[r1] * g_dinv[c1];
        int p0 = g_ptr[c0] + atomicAdd(&g_cur[c0], 1);
        int p1 = g_ptr[c1] + atomicAdd(&g_cur[c1], 1);
        if (p0 < EMAX) g_edge[p0] = make_int2(r0, __float_as_int(d0));
        if (p1 < EMAX) g_edge[p1] = make_int2(r1, __float_as_int(d1));
    } else if (i < T + n) {
        int c = i - T;
        int pos = g_ptr[c] + g_deg[c];
        float dv = g_dinv[c];
        if (pos < EMAX)
            g_edge[pos] = make_int2(c, __float_as_int(dv * dv));
    }
}

// convert x to fp16 into B0 (vectorized)
__global__ void xhalf_kernel(const float* __restrict__ x, int total4) {
    int i = blockIdx.x * blockDim.x + threadIdx.x;
    if (i < total4) {
        float4 v = ((const float4*)x)[i];
        half2* D = (half2*)g_hbuf[0];
        D[i * 2 + 0] = __floats2half2_rn(v.x, v.y);
        D[i * 2 + 1] = __floats2half2_rn(v.z, v.w);
    }
}

// ---- weight preprocessing: fp16 round + m16n8k16 fragment permutation -----
__device__ __forceinline__ void permWh(__half* dst, const float* __restrict__ W,
                                       int o, int ktbits) {
    int h    = o & 7;
    int lane = (o >> 3) & 31;
    int c    = (o >> 8) & 3;
    int wn2  = (o >> 10) & 1;
    int kk2  = (o >> 11) & 1;
    int rest = o >> 12;
    int kt   = rest & ((1 << ktbits) - 1);
    int nb   = rest >> ktbits;
    int tg = lane & 3, gp = lane >> 2;
    int nt = c * 2 + (h >> 2), hw = h & 3;
    int k  = kt * 32 + kk2 * 16 + (hw >> 1) * 8 + tg * 2 + (hw & 1);
    int n  = nb * 128 + wn2 * 64 + nt * 8 + gp;
    dst[o] = __float2half(W[k * CDIM + n]);
}

__global__ void wround_kernel(const float* __restrict__ W1,
                              const float* __restrict__ W2,
                              const float* __restrict__ W3,
                              const float* __restrict__ W4, int n1) {
    int o = blockIdx.x * blockDim.x + threadIdx.x;
    if (o < CDIM * CDIM) {
        permWh(g_wh[1], W2, o, 4);
        permWh(g_wh[2], W3, o, 4);
        permWh(g_wh[3], W4, o, 4);
        if (o < n1) permWh(g_wh[0], W1, o, 3);   // K=256 -> KT=8
    }
}

// ------------------------------- CSR SpMM ----------------------------------
// fp16 gather, fp32 accum, fp16 write; packed edges; unroll 4.
// Optional bias+relu epilogue (used by layer 1 only).
__global__ void spmm_h(int srcsel, int dstsel, int c8,
                       const float* __restrict__ bias, int relu)
{
    int v = blockIdx.x;
    int t = threadIdx.x;
    const uint4* S = (const uint4*)g_hbuf[srcsel];
    uint4* D = (uint4*)g_hbuf[dstsel];

    int beg = g_ptr[v], end = g_ptr[v + 1];
    float f[8];
    #pragma unroll
    for (int j = 0; j < 8; j++) f[j] = 0.f;

    int e = beg;
    for (; e + 3 < end; e += 4) {
        int2 e0 = g_edge[e],     e1 = g_edge[e + 1];
        int2 e2 = g_edge[e + 2], e3 = g_edge[e + 3];
        uint4 u0 = S[e0.x * c8 + t];
        uint4 u1 = S[e1.x * c8 + t];
        uint4 u2 = S[e2.x * c8 + t];
        uint4 u3 = S[e3.x * c8 + t];
        float w0 = __int_as_float(e0.y), w1 = __int_as_float(e1.y);
        float w2 = __int_as_float(e2.y), w3 = __int_as_float(e3.y);
        const half2* p0 = (const half2*)&u0;
        const half2* p1 = (const half2*)&u1;
        const half2* p2 = (const half2*)&u2;
        const half2* p3 = (const half2*)&u3;
        #pragma unroll
        for (int q = 0; q < 4; q++) {
            float2 a = __half22float2(p0[q]);
            float2 b = __half22float2(p1[q]);
            float2 cc = __half22float2(p2[q]);
            float2 dd = __half22float2(p3[q]);
            f[q * 2 + 0] += w0 * a.x + w1 * b.x + w2 * cc.x + w3 * dd.x;
            f[q * 2 + 1] += w0 * a.y + w1 * b.y + w2 * cc.y + w3 * dd.y;
        }
    }
    for (; e < end; e++) {
        int2 e0 = g_edge[e];
        float w0 = __int_as_float(e0.y);
        uint4 u0 = S[e0.x * c8 + t];
        const half2* p0 = (const half2*)&u0;
        #pragma unroll
        for (int q = 0; q < 4; q++) {
            float2 a = __half22float2(p0[q]);
            f[q * 2 + 0] += w0 * a.x;
            f[q * 2 + 1] += w0 * a.y;
        }
    }

    if (bias) {
        float4 bb0 = ((const float4*)bias)[t * 2];
        float4 bb1 = ((const float4*)bias)[t * 2 + 1];
        f[0] += bb0.x; f[1] += bb0.y; f[2] += bb0.z; f[3] += bb0.w;
        f[4] += bb1.x; f[5] += bb1.y; f[6] += bb1.z; f[7] += bb1.w;
    }
    if (relu) {
        #pragma unroll
        for (int j = 0; j < 8; j++) f[j] = fmaxf(f[j], 0.f);
    }

    uint4 o;
    half2* op = (half2*)&o;
    #pragma unroll
    for (int q = 0; q < 4; q++)
        op[q] = __floats2half2_rn(f[q * 2], f[q * 2 + 1]);
    D[v * c8 + t] = o;
}

// --------------------------- fp16 GEMM (mma.sync) --------------------------

__device__ __forceinline__ void mma_f16(float* c, const uint32_t* a,
                                        uint32_t b0, uint32_t b1) {
    asm volatile(
        "mma.sync.aligned.m16n8k16.row.col.f32.f16.f16.f32 "
        "{%0,%1,%2,%3}, {%4,%5,%6,%7}, {%8,%9}, {%0,%1,%2,%3};"
        : "+f"(c[0]), "+f"(c[1]), "+f"(c[2]), "+f"(c[3])
        : "r"(a[0]), "r"(a[1]), "r"(a[2]), "r"(a[3]), "r"(b0), "r"(b1));
}

#define AROWH 40   // A smem row stride in halves (80 B)

__global__ __launch_bounds__(128)
void gemm_h(const __half* __restrict__ Wh, const float* __restrict__ bias,
            float* __restrict__ dout, int M, int K, int insel, int outsel,
            int relu)
{
    __shared__ __align__(16) __half Ah[3][64 * AROWH];  // 5120 B / stage
    __shared__ __align__(16) __half Bh[3][4096];        // 8192 B / stage
    __shared__ float sbias[128];

    const __half* A = g_hbuf[insel];
    __half* C16 = (outsel < 0) ? nullptr : g_hbuf[outsel];

    int tid  = threadIdx.x;
    int bm   = blockIdx.x * 64;
    int nb   = blockIdx.y;
    int bn   = nb * 128;
    int wid  = tid >> 5, lane = tid & 31;
    int wm   = (wid >> 1) * 32;
    int wn   = (wid & 1) * 64;
    int wn2  = wid & 1;
    int tg   = lane & 3, gp = lane >> 2;

    sbias[tid] = bias ? bias[bn + tid] : 0.f;

    float acc[2][8][4];
    #pragma unroll
    for (int mt = 0; mt < 2; mt++)
        #pragma unroll
        for (int nt = 0; nt < 8; nt++)
            #pragma unroll
            for (int q = 0; q < 4; q++) acc[mt][nt][q] = 0.f;

    int a_row = tid >> 2, a_seg = tid & 3;
    int gr0 = bm + a_row;      if (gr0 >= M) gr0 = M - 1;
    int gr1 = bm + a_row + 32; if (gr1 >= M) gr1 = M - 1;

    uint32_t AhB[3], BhB[3];
    uint32_t sa0[3], sa1[3];
    #pragma unroll
    for (int s = 0; s < 3; s++) {
        AhB[s] = smem_u32(&Ah[s][0]);
        BhB[s] = smem_u32(&Bh[s][0]);
        sa0[s] = AhB[s] + (a_row * AROWH + a_seg * 8) * 2;
        sa1[s] = sa0[s] + 32 * AROWH * 2;
    }

    int lrow  = (lane & 7) + ((lane >> 3) & 1) * 8;
    int lcol  = (lane >> 4) & 1;
    uint32_t lmoff[2];
    #pragma unroll
    for (int mt = 0; mt < 2; mt++)
        lmoff[mt] = ((wm + mt * 16 + lrow) * AROWH) * 2 + lcol * 16;

    int ktiles = K >> 5;

    auto prefetch = [&](int kt) {
        int s  = kt % 3;
        const __half* a0p = A + (size_t)gr0 * K + kt * 32 + a_seg * 8;
        const __half* a1p = A + (size_t)gr1 * K + kt * 32 + a_seg * 8;
        CP_ASYNC16(sa0[s], a0p);
        CP_ASYNC16(sa1[s], a1p);
        const __half* src = Wh + (((size_t)(nb * ktiles + kt)) << 12) + (size_t)tid * 8;
        uint32_t bd = BhB[s] + tid * 16;
        #pragma unroll
        for (int i = 0; i < 4; i++)
            CP_ASYNC16(bd + i * 2048, src + i * 1024);
        CP_COMMIT();
    };

    prefetch(0);
    if (ktiles > 1) prefetch(1); else CP_COMMIT();

    for (int kt = 0; kt < ktiles; kt++) {
        if (kt + 1 < ktiles) CP_WAIT1(); else CP_WAIT0();
        __syncthreads();

        int buf = kt % 3;
        #pragma unroll
        for (int kk2 = 0; kk2 < 2; kk2++) {
            uint32_t a[2][4];
            #pragma unroll
            for (int mt = 0; mt < 2; mt++)
                LDMATRIX_X4(a[mt][0], a[mt][1], a[mt][2], a[mt][3],
                            AhB[buf] + lmoff[mt] + kk2 * 32);
            uint32_t b[8][2];
            #pragma unroll
            for (int c = 0; c < 4; c++) {
                uint32_t q0, q1, q2, q3;
                LDS128U(q0, q1, q2, q3,
                        BhB[buf] + ((kk2 * 2 + wn2) * 4 + c) * 512 + lane * 16);
                b[c * 2 + 0][0] = q0; b[c * 2 + 0][1] = q1;
                b[c * 2 + 1][0] = q2; b[c * 2 + 1][1] = q3;
            }
            #pragma unroll
            for (int mt = 0; mt < 2; mt++)
                #pragma unroll
                for (int nt = 0; nt < 8; nt++)
                    mma_f16(acc[mt][nt], a[mt], b[nt][0], b[nt][1]);
        }

        if (kt + 2 < ktiles) prefetch(kt + 2);
    }

    // epilogue: + bias (smem), optional relu; fp16 to g_hbuf or fp32 to dout
    #pragma unroll
    for (int mt = 0; mt < 2; mt++) {
        #pragma unroll
        for (int nt = 0; nt < 8; nt++) {
            int r = bm + wm + mt * 16 + gp;
            int cl = wn + nt * 8 + tg * 2;
            int c = bn + cl;
            float bb0 = sbias[cl], bb1 = sbias[cl + 1];
            float v0 = acc[mt][nt][0] + bb0, v1 = acc[mt][nt][1] + bb1;
            float v2 = acc[mt][nt][2] + bb0, v3 = acc[mt][nt][3] + bb1;
            if (relu) {
                v0 = fmaxf(v0, 0.f); v1 = fmaxf(v1, 0.f);
                v2 = fmaxf(v2, 0.f); v3 = fmaxf(v3, 0.f);
            }
            if (outsel < 0) {
                if (r < M)     *(float2*)&dout[(size_t)r * CDIM + c]       = make_float2(v0, v1);
                if (r + 8 < M) *(float2*)&dout[(size_t)(r + 8) * CDIM + c] = make_float2(v2, v3);
            } else {
                if (r < M)     *(half2*)&C16[(size_t)r * CDIM + c]       = __floats2half2_rn(v0, v1);
                if (r + 8 < M) *(half2*)&C16[(size_t)(r + 8) * CDIM + c] = __floats2half2_rn(v2, v3);
            }
        }
    }
}

// ------------------------------- driver ------------------------------------

extern "C" void kernel_launch(void* const* d_in, const int* in_sizes, int n_in,
                              void* d_out, int out_size)
{
    const float* x  = (const float*)d_in[0];
    const int*   ei = (const int*)d_in[1];      // int64 downcast to int32
    const float* W1 = (const float*)d_in[2];
    const float* b1 = (const float*)d_in[3];
    const float* W2 = (const float*)d_in[4];
    const float* b2 = (const float*)d_in[5];
    const float* W3 = (const float*)d_in[6];
    const float* b3 = (const float*)d_in[7];
    const float* W4 = (const float*)d_in[8];
    const float* b4 = (const float*)d_in[9];
    float* out = (float*)d_out;

    int Cin = in_sizes[2] / CDIM;         // 256
    int N   = in_sizes[0] / Cin;          // 10000
    int E   = in_sizes[1] / 2;            // 160000
    int nc  = (N + 511) / 512;            // 20 chunks

    static __half* wh_host[4] = {nullptr, nullptr, nullptr, nullptr};
    static void* deg_p = nullptr; static void* cur_p = nullptr;
    static void* st_p = nullptr;
    static cudaStream_t sB = nullptr;
    static cudaEvent_t evFork = nullptr, evJoin = nullptr;
    if (!wh_host[0]) {
        void* p;
        cudaGetSymbolAddress(&p, g_wh);
        for (int l = 0; l < 4; l++)
            wh_host[l] = (__half*)p + (size_t)l * CDIM * CDIM;
        cudaGetSymbolAddress(&deg_p, g_deg);
        cudaGetSymbolAddress(&cur_p, g_cur);
        cudaGetSymbolAddress(&st_p, g_state);
        cudaStreamCreateWithFlags(&sB, cudaStreamNonBlocking);
        cudaEventCreateWithFlags(&evFork, cudaEventDisableTiming);
        cudaEventCreateWithFlags(&evJoin, cudaEventDisableTiming);
    }

    dim3 ggrid((N + 63) / 64, CDIM / 128);   // (157, 4)

    // fork: stream B does the graph-independent layer-1 GEMM chain
    cudaEventRecord(evFork, 0);
    cudaStreamWaitEvent(sB, evFork, 0);
    wround_kernel<<<(CDIM * CDIM + 255) / 256, 256, 0, sB>>>(W1, W2, W3, W4,
                                                            Cin * CDIM);
    xhalf_kernel<<<(N * Cin / 4 + 255) / 256, 256, 0, sB>>>(x, N * Cin / 4);
    // Y1 = x @ W1 (no bias/relu): B0 -> B1
    gemm_h<<<ggrid, 128, 0, sB>>>(wh_host[0], nullptr, nullptr, N, Cin, 0, 1, 0);
    cudaEventRecord(evJoin, sB);

    // main stream: graph preprocessing (concurrent with stream B)
    cudaMemsetAsync(deg_p, 0, N * sizeof(int), 0);
    cudaMemsetAsync(cur_p, 0, N * sizeof(int), 0);
    cudaMemsetAsync(st_p, 0, 64 * sizeof(unsigned), 0);
    count_kernel<<<(E / 2 + 255) / 256, 256>>>(ei, E, N);
    scan_fused<<<nc, 512>>>(N);
    fill_kernel<<<(E / 2 + N + 255) / 256, 256>>>(ei, E, N);
    cudaStreamWaitEvent(0, evJoin, 0);   // join: need Y1 + graph

    // layer 1 aggregation: h1 = relu(A @ Y1 + b1): B1 -> B0
    spmm_h<<<N, CDIM / 8>>>(1, 0, CDIM / 8, b1, 1);
    // layer 2
    spmm_h<<<N, CDIM / 8>>>(0, 1, CDIM / 8, nullptr, 0);
    gemm_h<<<ggrid, 128>>>(wh_host[1], b2, nullptr, N, CDIM, 1, 0, 1);
    // layer 3
    spmm_h<<<N, CDIM / 8>>>(0, 1, CDIM / 8, nullptr, 0);
    gemm_h<<<ggrid, 128>>>(wh_host[2], b3, nullptr, N, CDIM, 1, 0, 1);
    // layer 4 (no relu, fp32 out)
    spmm_h<<<N, CDIM / 8>>>(0, 1, CDIM / 8, nullptr, 0);
    gemm_h<<<ggrid, 128>>>(wh_host[3], b4, out, N, CDIM, 1, -1, 0);
}